// round 5
// baseline (speedup 1.0000x reference)
#include <cuda_runtime.h>
#include <math.h>

#define N_MAX 100000
#define E_MAX 1600000
#define DH 128
#define DOUT 40
#define BN_EPS 1e-5f
#define SCAN_B 1024
#define NB_MAX 128   // ceil(N_MAX/1024) = 98

// ---------------- scratch (static device globals; no allocation) ----------------
__device__ int   g_deg[N_MAX];
__device__ int   g_incl[N_MAX];
__device__ int   g_bsum[NB_MAX];
__device__ int   g_bscan[NB_MAX];
__device__ int   g_rowstart[N_MAX];
__device__ int   g_cursor[N_MAX];
__device__ float g_disq[N_MAX];
__device__ int2  g_csr[E_MAX];
__device__ float g_t[(size_t)N_MAX * DH];
__device__ float g_h[(size_t)N_MAX * DH];
__device__ float g_stats[2 * DH];
__device__ float g_scale[DH];
__device__ float g_shift[DH];

// ---------------- helpers ----------------
__device__ __forceinline__ void red_add_v4(float* p, float4 v) {
    asm volatile("red.global.add.v4.f32 [%0], {%1,%2,%3,%4};"
                 :: "l"(p), "f"(v.x), "f"(v.y), "f"(v.z), "f"(v.w) : "memory");
}
// cvt.rna.tf32.f32 needs a .b32 (integer) destination register.
__device__ __forceinline__ float tf32_rn(float f) {
    unsigned r;
    asm("cvt.rna.tf32.f32 %0, %1;" : "=r"(r) : "f"(f));
    return __int_as_float((int)r);
}
__device__ __forceinline__ void mma_tf32(float* d, const float* a, const float* b) {
    asm volatile(
        "mma.sync.aligned.m16n8k8.row.col.f32.tf32.tf32.f32 "
        "{%0,%1,%2,%3}, {%4,%5,%6,%7}, {%8,%9}, {%0,%1,%2,%3};\n"
        : "+f"(d[0]), "+f"(d[1]), "+f"(d[2]), "+f"(d[3])
        : "r"(__float_as_int(a[0])), "r"(__float_as_int(a[1])),
          "r"(__float_as_int(a[2])), "r"(__float_as_int(a[3])),
          "r"(__float_as_int(b[0])), "r"(__float_as_int(b[1])));
}

// ---------------- CSR build ----------------
__global__ void zero_deg(int n) {
    int i = blockIdx.x * blockDim.x + threadIdx.x;
    if (i < n) g_deg[i] = 0;
}
__global__ void count_deg(const int* __restrict__ dst, int e) {
    int i = blockIdx.x * blockDim.x + threadIdx.x;
    if (i < e) atomicAdd(&g_deg[dst[i]], 1);
}
__global__ void calc_disq(int n) {
    int i = blockIdx.x * blockDim.x + threadIdx.x;
    if (i < n) g_disq[i] = rsqrtf(1.0f + (float)g_deg[i]);
}
__global__ void scan1(int n) {
    __shared__ int sm[SCAN_B];
    int tid = threadIdx.x;
    int i = blockIdx.x * SCAN_B + tid;
    sm[tid] = (i < n) ? g_deg[i] : 0;
    __syncthreads();
#pragma unroll
    for (int off = 1; off < SCAN_B; off <<= 1) {
        int t = (tid >= off) ? sm[tid - off] : 0;
        __syncthreads();
        sm[tid] += t;
        __syncthreads();
    }
    if (i < n) g_incl[i] = sm[tid];
    if (tid == SCAN_B - 1) g_bsum[blockIdx.x] = sm[tid];
}
__global__ void scan2(int nb) {
    __shared__ int sm[NB_MAX];
    int tid = threadIdx.x;
    sm[tid] = (tid < nb) ? g_bsum[tid] : 0;
    __syncthreads();
#pragma unroll
    for (int off = 1; off < NB_MAX; off <<= 1) {
        int t = (tid >= off) ? sm[tid - off] : 0;
        __syncthreads();
        sm[tid] += t;
        __syncthreads();
    }
    if (tid < nb) g_bscan[tid] = sm[tid];
}
__global__ void scan3(int n) {
    int i = blockIdx.x * blockDim.x + threadIdx.x;
    if (i < n) {
        int b = i / SCAN_B;
        int base = (b > 0) ? g_bscan[b - 1] : 0;
        int rs = base + g_incl[i] - g_deg[i];
        g_rowstart[i] = rs;
        g_cursor[i]   = rs;
    }
}
__global__ void fill_csr(const int* __restrict__ src, const int* __restrict__ dst, int e) {
    int i = blockIdx.x * blockDim.x + threadIdx.x;
    if (i < e) {
        int s = src[i], d = dst[i];
        int pos = atomicAdd(&g_cursor[d], 1);
        float w = g_disq[s] * g_disq[d];
        g_csr[pos] = make_int2(s, __float_as_int(w));
    }
}
__global__ void zero_stats() {
    int i = threadIdx.x;
    if (i < 2 * DH) g_stats[i] = 0.0f;
}

// ---------------- GEMM 128x128 via tf32 tensor cores (3xTF32), fused BN+ReLU on load ----------------
// block tile 128x128, 512 threads (16 warps in 4x4), warp tile 32x32, K-chunks of 16
#define XPAD 20
#define WPAD 132
__global__ void __launch_bounds__(512, 1) gemm128_tc(const float* __restrict__ Xin,
                                                     const float* __restrict__ W,
                                                     int n, int use_bn) {
    __shared__ float Xhi[128][XPAD];
    __shared__ float Xlo[128][XPAD];
    __shared__ float Whi[16][WPAD];
    __shared__ float Wlo[16][WPAD];

    const float* X = Xin ? Xin : g_h;
    int tid  = threadIdx.x;
    int lane = tid & 31;
    int wid  = tid >> 5;
    int warp_m = wid & 3;      // 4 m-tiles of 32 rows
    int warp_n = wid >> 2;     // 4 n-tiles of 32 cols
    int g  = lane >> 2;        // group id 0..7
    int tg = lane & 3;         // thread in group 0..3
    int row0 = blockIdx.x * 128;

    float acc[2][4][4];
#pragma unroll
    for (int mt = 0; mt < 2; mt++)
#pragma unroll
        for (int nt = 0; nt < 4; nt++)
#pragma unroll
            for (int k = 0; k < 4; k++) acc[mt][nt][k] = 0.f;

    for (int kc = 0; kc < 8; kc++) {
        // ---- load X chunk 128x16 (512 float4, 1/thread), split hi/lo ----
        {
            int r  = tid >> 2;
            int c4 = tid & 3;
            int gr = row0 + r;
            float4 v = make_float4(0.f, 0.f, 0.f, 0.f);
            if (gr < n) v = *(const float4*)(X + (size_t)gr * DH + kc * 16 + c4 * 4);
            if (use_bn) {
                float4 sc = *(const float4*)(g_scale + kc * 16 + c4 * 4);
                float4 sh = *(const float4*)(g_shift + kc * 16 + c4 * 4);
                v.x = fmaxf(0.f, fmaf(v.x, sc.x, sh.x));
                v.y = fmaxf(0.f, fmaf(v.y, sc.y, sh.y));
                v.z = fmaxf(0.f, fmaf(v.z, sc.z, sh.z));
                v.w = fmaxf(0.f, fmaf(v.w, sc.w, sh.w));
            }
            float4 hi, lo;
            hi.x = tf32_rn(v.x); lo.x = tf32_rn(v.x - hi.x);
            hi.y = tf32_rn(v.y); lo.y = tf32_rn(v.y - hi.y);
            hi.z = tf32_rn(v.z); lo.z = tf32_rn(v.z - hi.z);
            hi.w = tf32_rn(v.w); lo.w = tf32_rn(v.w - hi.w);
            *(float4*)&Xhi[r][c4 * 4] = hi;   // stride 20 floats = 80B, 16B aligned
            *(float4*)&Xlo[r][c4 * 4] = lo;
        }
        // ---- load W chunk 16x128 (512 float4, 1/thread), split hi/lo ----
        {
            int r  = tid >> 5;
            int c4 = lane;
            float4 v = *(const float4*)(W + (size_t)(kc * 16 + r) * DH + c4 * 4);
            float4 hi, lo;
            hi.x = tf32_rn(v.x); lo.x = tf32_rn(v.x - hi.x);
            hi.y = tf32_rn(v.y); lo.y = tf32_rn(v.y - hi.y);
            hi.z = tf32_rn(v.z); lo.z = tf32_rn(v.z - hi.z);
            hi.w = tf32_rn(v.w); lo.w = tf32_rn(v.w - hi.w);
            *(float4*)&Whi[r][c4 * 4] = hi;   // stride 132 floats = 528B, 16B aligned
            *(float4*)&Wlo[r][c4 * 4] = lo;
        }
        __syncthreads();

#pragma unroll
        for (int ks = 0; ks < 2; ks++) {
            int kb = ks * 8;
            float ahi[2][4], alo[2][4];
#pragma unroll
            for (int mt = 0; mt < 2; mt++) {
                int r = warp_m * 32 + mt * 16 + g;
                ahi[mt][0] = Xhi[r][kb + tg];
                ahi[mt][1] = Xhi[r + 8][kb + tg];
                ahi[mt][2] = Xhi[r][kb + tg + 4];
                ahi[mt][3] = Xhi[r + 8][kb + tg + 4];
                alo[mt][0] = Xlo[r][kb + tg];
                alo[mt][1] = Xlo[r + 8][kb + tg];
                alo[mt][2] = Xlo[r][kb + tg + 4];
                alo[mt][3] = Xlo[r + 8][kb + tg + 4];
            }
            float bhi[4][2], blo[4][2];
#pragma unroll
            for (int nt = 0; nt < 4; nt++) {
                int c = warp_n * 32 + nt * 8 + g;
                bhi[nt][0] = Whi[kb + tg][c];
                bhi[nt][1] = Whi[kb + tg + 4][c];
                blo[nt][0] = Wlo[kb + tg][c];
                blo[nt][1] = Wlo[kb + tg + 4][c];
            }
#pragma unroll
            for (int mt = 0; mt < 2; mt++)
#pragma unroll
                for (int nt = 0; nt < 4; nt++) {
                    mma_tf32(acc[mt][nt], ahi[mt], blo[nt]);
                    mma_tf32(acc[mt][nt], alo[mt], bhi[nt]);
                    mma_tf32(acc[mt][nt], ahi[mt], bhi[nt]);
                }
        }
        __syncthreads();
    }

    // ---- store ----
#pragma unroll
    for (int mt = 0; mt < 2; mt++)
#pragma unroll
        for (int nt = 0; nt < 4; nt++) {
            int r = row0 + warp_m * 32 + mt * 16 + g;
            int c = warp_n * 32 + nt * 8 + tg * 2;
            if (r < n)
                *(float2*)(g_t + (size_t)r * DH + c) =
                    make_float2(acc[mt][nt][0], acc[mt][nt][1]);
            if (r + 8 < n)
                *(float2*)(g_t + (size_t)(r + 8) * DH + c) =
                    make_float2(acc[mt][nt][2], acc[mt][nt][3]);
        }
}

// ---------------- GEMM 128x40 (input = g_h with fused BN+ReLU), writes g_t[n,40] ----------------
__global__ void __launch_bounds__(240) gemm40(const float* __restrict__ W, int n) {
    __shared__ float ws[DH * DOUT];
    __shared__ float xs[48][32];

    int tx  = threadIdx.x;
    int ty  = threadIdx.y;
    int tid = ty * 40 + tx;

    for (int i = tid; i < DH * DOUT; i += 240) ws[i] = W[i];

    int row0 = blockIdx.x * 48;
    float acc[8];
#pragma unroll
    for (int r = 0; r < 8; r++) acc[r] = 0.f;

    for (int kc = 0; kc < 4; kc++) {
        for (int i = tid; i < 384; i += 240) {
            int r  = i >> 3;
            int c4 = i & 7;
            int gr = row0 + r;
            float4 v = make_float4(0.f, 0.f, 0.f, 0.f);
            if (gr < n) v = *(const float4*)(g_h + (size_t)gr * DH + kc * 32 + c4 * 4);
            float4 sc = *(const float4*)(g_scale + kc * 32 + c4 * 4);
            float4 sh = *(const float4*)(g_shift + kc * 32 + c4 * 4);
            v.x = fmaxf(0.f, fmaf(v.x, sc.x, sh.x));
            v.y = fmaxf(0.f, fmaf(v.y, sc.y, sh.y));
            v.z = fmaxf(0.f, fmaf(v.z, sc.z, sh.z));
            v.w = fmaxf(0.f, fmaf(v.w, sc.w, sh.w));
            *(float4*)&xs[r][c4 * 4] = v;
        }
        __syncthreads();
#pragma unroll
        for (int kk = 0; kk < 32; kk++) {
            float wv = ws[(kc * 32 + kk) * DOUT + tx];
#pragma unroll
            for (int r8 = 0; r8 < 8; r8++)
                acc[r8] = fmaf(xs[ty * 8 + r8][kk], wv, acc[r8]);
        }
        __syncthreads();
    }
#pragma unroll
    for (int r8 = 0; r8 < 8; r8++) {
        int gr = row0 + ty * 8 + r8;
        if (gr < n) g_t[(size_t)gr * DOUT + tx] = acc[r8];
    }
}

// ---------------- fused aggregate + combine + BN stats, F=128. One warp per row. ----------------
__global__ void __launch_bounds__(256) agg_combine128(const float* __restrict__ b, int n) {
    int lane = threadIdx.x & 31;
    int wip  = threadIdx.x >> 5;
    const float4* T = (const float4*)g_t;
    float4 bc = ((const float4*)b)[lane];

    float4 ssum = make_float4(0.f, 0.f, 0.f, 0.f);
    float4 ssq  = make_float4(0.f, 0.f, 0.f, 0.f);

    for (int row = blockIdx.x * 8 + wip; row < n; row += gridDim.x * 8) {
        int start = g_rowstart[row];
        int cnt   = g_deg[row];
        float4 acc = make_float4(0.f, 0.f, 0.f, 0.f);
        for (int j = start; j < start + cnt; j++) {
            int2  pr = g_csr[j];
            float w  = __int_as_float(pr.y);
            float4 v = __ldg(T + (size_t)pr.x * 32 + lane);
            acc.x = fmaf(w, v.x, acc.x);
            acc.y = fmaf(w, v.y, acc.y);
            acc.z = fmaf(w, v.z, acc.z);
            acc.w = fmaf(w, v.w, acc.w);
        }
        float dq = g_disq[row];
        float sn = dq * dq;
        float4 t = __ldg(T + (size_t)row * 32 + lane);
        float4 h;
        h.x = fmaf(sn, t.x, acc.x) + bc.x;
        h.y = fmaf(sn, t.y, acc.y) + bc.y;
        h.z = fmaf(sn, t.z, acc.z) + bc.z;
        h.w = fmaf(sn, t.w, acc.w) + bc.w;
        ((float4*)g_h)[(size_t)row * 32 + lane] = h;
        ssum.x += h.x; ssum.y += h.y; ssum.z += h.z; ssum.w += h.w;
        ssq.x = fmaf(h.x, h.x, ssq.x); ssq.y = fmaf(h.y, h.y, ssq.y);
        ssq.z = fmaf(h.z, h.z, ssq.z); ssq.w = fmaf(h.w, h.w, ssq.w);
    }

    __shared__ float4 sh1[8][32];
    __shared__ float4 sh2[8][32];
    sh1[wip][lane] = ssum;
    sh2[wip][lane] = ssq;
    __syncthreads();
    if (wip == 0) {
        float4 a = sh1[0][lane], q = sh2[0][lane];
#pragma unroll
        for (int w = 1; w < 8; w++) {
            float4 a2 = sh1[w][lane], q2 = sh2[w][lane];
            a.x += a2.x; a.y += a2.y; a.z += a2.z; a.w += a2.w;
            q.x += q2.x; q.y += q2.y; q.z += q2.z; q.w += q2.w;
        }
        red_add_v4(g_stats + lane * 4, a);
        red_add_v4(g_stats + DH + lane * 4, q);
    }
}

// ---------------- BN finalize ----------------
__global__ void bn_finalize(const float* __restrict__ gam, const float* __restrict__ bet, int n) {
    int c = threadIdx.x;
    if (c < DH) {
        float inv_n = 1.0f / (float)n;
        float mu  = g_stats[c] * inv_n;
        float var = g_stats[DH + c] * inv_n - mu * mu;
        float rs  = rsqrtf(var + BN_EPS);
        float sc  = rs * gam[c];
        g_scale[c] = sc;
        g_shift[c] = bet[c] - mu * sc;
    }
}

// ---------------- fused aggregate + combine + log_softmax, F=40. One warp per row. ----------------
__global__ void __launch_bounds__(256) agg40_lsm(const float* __restrict__ b2,
                                                 float* __restrict__ out, int n) {
    int lane = threadIdx.x & 31;
    int wip  = threadIdx.x >> 5;
    const float4* T = (const float4*)g_t;
    bool active = (lane < 10);
    float4 bc = make_float4(0.f, 0.f, 0.f, 0.f);
    if (active) bc = ((const float4*)b2)[lane];

    for (int row = blockIdx.x * 8 + wip; row < n; row += gridDim.x * 8) {
        int start = g_rowstart[row];
        int cnt   = g_deg[row];
        float4 acc = make_float4(0.f, 0.f, 0.f, 0.f);
        for (int j = start; j < start + cnt; j++) {
            int2  pr = g_csr[j];
            float w  = __int_as_float(pr.y);
            if (active) {
                float4 v = __ldg(T + (size_t)pr.x * 10 + lane);
                acc.x = fmaf(w, v.x, acc.x);
                acc.y = fmaf(w, v.y, acc.y);
                acc.z = fmaf(w, v.z, acc.z);
                acc.w = fmaf(w, v.w, acc.w);
            }
        }
        float dq = g_disq[row];
        float sn = dq * dq;
        float4 h = make_float4(-1e30f, -1e30f, -1e30f, -1e30f);
        if (active) {
            float4 t = __ldg(T + (size_t)row * 10 + lane);
            h.x = fmaf(sn, t.x, acc.x) + bc.x;
            h.y = fmaf(sn, t.y, acc.y) + bc.y;
            h.z = fmaf(sn, t.z, acc.z) + bc.z;
            h.w = fmaf(sn, t.w, acc.w) + bc.w;
        }
        float m = fmaxf(fmaxf(h.x, h.y), fmaxf(h.z, h.w));
#pragma unroll
        for (int o = 16; o; o >>= 1) m = fmaxf(m, __shfl_xor_sync(0xFFFFFFFFu, m, o));
        float se = 0.f;
        if (active)
            se = expf(h.x - m) + expf(h.y - m) + expf(h.z - m) + expf(h.w - m);
#pragma unroll
        for (int o = 16; o; o >>= 1) se += __shfl_xor_sync(0xFFFFFFFFu, se, o);
        float lse = m + logf(se);
        if (active) {
            float4 r = make_float4(h.x - lse, h.y - lse, h.z - lse, h.w - lse);
            ((float4*)out)[(size_t)row * 10 + lane] = r;
        }
    }
}

// ---------------- launch ----------------
extern "C" void kernel_launch(void* const* d_in, const int* in_sizes, int n_in,
                              void* d_out, int out_size) {
    const float* x   = (const float*)d_in[0];
    const int*   src = (const int*)d_in[1];
    const int*   dst = (const int*)d_in[2];
    const float* W0  = (const float*)d_in[3];
    const float* b0  = (const float*)d_in[4];
    const float* W1  = (const float*)d_in[5];
    const float* b1  = (const float*)d_in[6];
    const float* W2  = (const float*)d_in[7];
    const float* b2  = (const float*)d_in[8];
    const float* g0  = (const float*)d_in[9];
    const float* be0 = (const float*)d_in[10];
    const float* g1  = (const float*)d_in[11];
    const float* be1 = (const float*)d_in[12];
    float* out = (float*)d_out;

    int n = in_sizes[0] / DH;
    int e = in_sizes[1];
    int nb = (n + SCAN_B - 1) / SCAN_B;

    int agg_blocks  = 1480;
    int gemm_blocks = (n + 127) / 128;

    // ---- CSR build (with layer-0 GEMM moved to launch index 3 for profiling) ----
    zero_deg<<<(n + 255) / 256, 256>>>(n);
    count_deg<<<(e + 255) / 256, 256>>>(dst, e);
    calc_disq<<<(n + 255) / 256, 256>>>(n);
    gemm128_tc<<<gemm_blocks, 512>>>(x, W0, n, 0);        // layer-0 GEMM (independent of CSR)
    scan1<<<nb, SCAN_B>>>(n);
    scan2<<<1, NB_MAX>>>(nb);
    scan3<<<(n + 255) / 256, 256>>>(n);
    fill_csr<<<(e + 255) / 256, 256>>>(src, dst, e);

    // ---- layer 0 (agg part) ----
    zero_stats<<<1, 256>>>();
    agg_combine128<<<agg_blocks, 256>>>(b0, n);
    bn_finalize<<<1, DH>>>(g0, be0, n);

    // ---- layer 1 ----
    gemm128_tc<<<gemm_blocks, 512>>>(nullptr, W1, n, 1);
    zero_stats<<<1, 256>>>();
    agg_combine128<<<agg_blocks, 256>>>(b1, n);
    bn_finalize<<<1, DH>>>(g1, be1, n);

    // ---- layer 2 ----
    gemm40<<<(n + 47) / 48, dim3(DOUT, 6)>>>(W2, n);
    agg40_lsm<<<agg_blocks, 256>>>(b2, out, n);
}

// round 7
// speedup vs baseline: 1.0553x; 1.0553x over previous
#include <cuda_runtime.h>
#include <math.h>

#define N_MAX 100000
#define E_MAX 1600000
#define DH 128
#define DOUT 40
#define BN_EPS 1e-5f
#define SCAN_B 1024
#define NB_MAX 128   // ceil(N_MAX/1024) = 98

// ---------------- scratch (static device globals; no allocation) ----------------
__device__ int   g_deg[N_MAX];
__device__ int   g_incl[N_MAX];
__device__ int   g_bsum[NB_MAX];
__device__ int   g_bscan[NB_MAX];
__device__ int   g_rowstart[N_MAX];
__device__ int   g_cursor[N_MAX];
__device__ float g_disq[N_MAX];
__device__ int2  g_csr[E_MAX];
__device__ float g_t[(size_t)N_MAX * DH];
__device__ float g_h[(size_t)N_MAX * DH];
__device__ float g_stats[2 * DH];
__device__ float g_scale[DH];
__device__ float g_shift[DH];

// ---------------- helpers ----------------
__device__ __forceinline__ void red_add_v4(float* p, float4 v) {
    asm volatile("red.global.add.v4.f32 [%0], {%1,%2,%3,%4};"
                 :: "l"(p), "f"(v.x), "f"(v.y), "f"(v.z), "f"(v.w) : "memory");
}
// cvt.rna.tf32.f32 needs a .b32 (integer) destination register.
__device__ __forceinline__ float tf32_rn(float f) {
    unsigned r;
    asm("cvt.rna.tf32.f32 %0, %1;" : "=r"(r) : "f"(f));
    return __int_as_float((int)r);
}
__device__ __forceinline__ void mma_tf32(float* d, const float* a, const float* b) {
    asm volatile(
        "mma.sync.aligned.m16n8k8.row.col.f32.tf32.tf32.f32 "
        "{%0,%1,%2,%3}, {%4,%5,%6,%7}, {%8,%9}, {%0,%1,%2,%3};\n"
        : "+f"(d[0]), "+f"(d[1]), "+f"(d[2]), "+f"(d[3])
        : "r"(__float_as_int(a[0])), "r"(__float_as_int(a[1])),
          "r"(__float_as_int(a[2])), "r"(__float_as_int(a[3])),
          "r"(__float_as_int(b[0])), "r"(__float_as_int(b[1])));
}

// ---------------- CSR build ----------------
__global__ void zero_deg(int n) {
    int i = blockIdx.x * blockDim.x + threadIdx.x;
    if (i < n) g_deg[i] = 0;
}
__global__ void count_deg(const int* __restrict__ dst, int e) {
    int i = blockIdx.x * blockDim.x + threadIdx.x;
    if (i < e) atomicAdd(&g_deg[dst[i]], 1);
}
__global__ void calc_disq(int n) {
    int i = blockIdx.x * blockDim.x + threadIdx.x;
    if (i < n) g_disq[i] = rsqrtf(1.0f + (float)g_deg[i]);
}
__global__ void scan1(int n) {
    __shared__ int sm[SCAN_B];
    int tid = threadIdx.x;
    int i = blockIdx.x * SCAN_B + tid;
    sm[tid] = (i < n) ? g_deg[i] : 0;
    __syncthreads();
#pragma unroll
    for (int off = 1; off < SCAN_B; off <<= 1) {
        int t = (tid >= off) ? sm[tid - off] : 0;
        __syncthreads();
        sm[tid] += t;
        __syncthreads();
    }
    if (i < n) g_incl[i] = sm[tid];
    if (tid == SCAN_B - 1) g_bsum[blockIdx.x] = sm[tid];
}
__global__ void scan2(int nb) {
    __shared__ int sm[NB_MAX];
    int tid = threadIdx.x;
    sm[tid] = (tid < nb) ? g_bsum[tid] : 0;
    __syncthreads();
#pragma unroll
    for (int off = 1; off < NB_MAX; off <<= 1) {
        int t = (tid >= off) ? sm[tid - off] : 0;
        __syncthreads();
        sm[tid] += t;
        __syncthreads();
    }
    if (tid < nb) g_bscan[tid] = sm[tid];
}
__global__ void scan3(int n) {
    int i = blockIdx.x * blockDim.x + threadIdx.x;
    if (i < n) {
        int b = i / SCAN_B;
        int base = (b > 0) ? g_bscan[b - 1] : 0;
        int rs = base + g_incl[i] - g_deg[i];
        g_rowstart[i] = rs;
        g_cursor[i]   = rs;
    }
}
__global__ void fill_csr(const int* __restrict__ src, const int* __restrict__ dst, int e) {
    int i = blockIdx.x * blockDim.x + threadIdx.x;
    if (i < e) {
        int s = src[i], d = dst[i];
        int pos = atomicAdd(&g_cursor[d], 1);
        float w = g_disq[s] * g_disq[d];
        g_csr[pos] = make_int2(s, __float_as_int(w));
    }
}
__global__ void zero_stats() {
    int i = threadIdx.x;
    if (i < 2 * DH) g_stats[i] = 0.0f;
}

// ============ GEMM 128x128 via 3xTF32 tensor cores, fragment-major smem ============
// 512 threads, 16 warps (4x4), warp tile 32x32, block tile 128x128, BK=16 (2 ks of 8).
// W (hi+lo) fully smem-resident in fragment layout; X double-buffered, 1 sync/iter.
//
// A-frag (m16k8): lane L=g*4+tg holds {X[g][tg], X[g+8][tg], X[g][tg+4], X[g+8][tg+4]}
//   stored as float4 per lane -> frag = 128 words, padded to 132.
// B-frag (k8n8):  lane L holds {W[tg][g], W[tg+4][g]}
//   stored as float2 per lane -> frag = 64 words, padded to 66.
#define WFRAG 66
#define XFRAG 132
#define XBUF  (16 * XFRAG)              // 16 frags (8 tm x 2 ks) per buffer = 2112 words
#define WTOT  (256 * WFRAG)             // 8 kc x 2 ks x 16 nt frags = 16896 words
// Xhi: 2 buffers, Xlo: 2 buffers -> 4*XBUF total for X
#define GEMM_SMEM_FLOATS (2 * WTOT + 4 * XBUF)
#define GEMM_SMEM_BYTES  (GEMM_SMEM_FLOATS * 4)   // 168960 B ~ 165 KB

__global__ void __launch_bounds__(512, 1) gemm128_tc(const float* __restrict__ Xin,
                                                     const float* __restrict__ W,
                                                     int n, int use_bn) {
    extern __shared__ float smem[];
    float* Whi = smem;
    float* Wlo = Whi + WTOT;
    float* Xhi = Wlo + WTOT;
    float* Xlo = Xhi + XBUF * 2;  // Xlo's two buffers follow Xhi's two buffers

    const float* X = Xin ? Xin : g_h;
    int tid  = threadIdx.x;
    int lane = tid & 31;
    int wid  = tid >> 5;
    int warp_m = wid & 3;
    int warp_n = wid >> 2;
    int row0 = blockIdx.x * 128;

    // X-load geometry for this thread (fixed): row r, float4 col c4
    int xr  = tid >> 2;          // 0..127
    int xc4 = tid & 3;           // 0..3  (k = c4*4 .. c4*4+3)
    int xtm   = xr >> 4;
    int xri   = xr & 15;
    int xks   = xc4 >> 1;
    int xslot = (xri >> 3) + 2 * (xc4 & 1);
    int xlaneb = (xri & 7) * 4;
    int xfbase = (xtm * 2 + xks) * XFRAG + xslot;   // + buf*XBUF + (xlaneb+j)*4

    // ---- prologue: stage full W (128x128) into fragment layout, hi+lo ----
#pragma unroll
    for (int t = 0; t < 8; t++) {
        int q  = tid + t * 512;          // float4 index, 4096 total
        int k  = q >> 5;                 // 0..127
        int c4 = q & 31;
        float4 v = *(const float4*)(W + (size_t)k * DH + c4 * 4);
        int kc = k >> 4;
        int ks = (k >> 3) & 1;
        int kjlow = k & 3;
        int slot  = (k >> 2) & 1;
        int nt = c4 >> 1;
        int base = ((kc * 2 + ks) * 16 + nt) * WFRAG + slot;
        int lb = (4 * (c4 & 1)) * 4 + kjlow;    // lane base: lane = (4*(c4&1)+j)*4 + kjlow
        float h0 = tf32_rn(v.x), h1 = tf32_rn(v.y), h2 = tf32_rn(v.z), h3 = tf32_rn(v.w);
        Whi[base + (lb + 0)  * 2] = h0;
        Whi[base + (lb + 4)  * 2] = h1;
        Whi[base + (lb + 8)  * 2] = h2;
        Whi[base + (lb + 12) * 2] = h3;
        Wlo[base + (lb + 0)  * 2] = tf32_rn(v.x - h0);
        Wlo[base + (lb + 4)  * 2] = tf32_rn(v.y - h1);
        Wlo[base + (lb + 8)  * 2] = tf32_rn(v.z - h2);
        Wlo[base + (lb + 12) * 2] = tf32_rn(v.w - h3);
    }

    // ---- helper lambda: load X float4 for chunk kc (BN-fused), returns value ----
    auto load_x = [&](int kc) -> float4 {
        int gr = row0 + xr;
        float4 v = make_float4(0.f, 0.f, 0.f, 0.f);
        if (gr < n) v = *(const float4*)(X + (size_t)gr * DH + kc * 16 + xc4 * 4);
        if (use_bn) {
            float4 sc = *(const float4*)(g_scale + kc * 16 + xc4 * 4);
            float4 sh = *(const float4*)(g_shift + kc * 16 + xc4 * 4);
            v.x = fmaxf(0.f, fmaf(v.x, sc.x, sh.x));
            v.y = fmaxf(0.f, fmaf(v.y, sc.y, sh.y));
            v.z = fmaxf(0.f, fmaf(v.z, sc.z, sh.z));
            v.w = fmaxf(0.f, fmaf(v.w, sc.w, sh.w));
        }
        return v;
    };
    auto store_x = [&](float4 v, int buf) {
        int base = buf * XBUF + xfbase;
        float h0 = tf32_rn(v.x), h1 = tf32_rn(v.y), h2 = tf32_rn(v.z), h3 = tf32_rn(v.w);
        Xhi[base + (xlaneb + 0) * 4] = h0;
        Xhi[base + (xlaneb + 1) * 4] = h1;
        Xhi[base + (xlaneb + 2) * 4] = h2;
        Xhi[base + (xlaneb + 3) * 4] = h3;
        Xlo[base + (xlaneb + 0) * 4] = tf32_rn(v.x - h0);
        Xlo[base + (xlaneb + 1) * 4] = tf32_rn(v.y - h1);
        Xlo[base + (xlaneb + 2) * 4] = tf32_rn(v.z - h2);
        Xlo[base + (xlaneb + 3) * 4] = tf32_rn(v.w - h3);
    };

    float acc[2][4][4];
#pragma unroll
    for (int mt = 0; mt < 2; mt++)
#pragma unroll
        for (int nt = 0; nt < 4; nt++)
#pragma unroll
            for (int k = 0; k < 4; k++) acc[mt][nt][k] = 0.f;

    // preload chunk 0 (sync also covers W prologue)
    store_x(load_x(0), 0);
    __syncthreads();

    int buf = 0;
    for (int kc = 0; kc < 8; kc++) {
        float4 xnext;
        if (kc < 7) xnext = load_x(kc + 1);

#pragma unroll
        for (int ks = 0; ks < 2; ks++) {
            float ahi[2][4], alo[2][4];
#pragma unroll
            for (int mt = 0; mt < 2; mt++) {
                int f = ((warp_m * 2 + mt) * 2 + ks) * XFRAG;
                *(float4*)ahi[mt] = *(const float4*)&Xhi[buf * XBUF + f + lane * 4];
                *(float4*)alo[mt] = *(const float4*)&Xlo[buf * XBUF + f + lane * 4];
            }
            float bhi[4][2], blo[4][2];
#pragma unroll
            for (int nt = 0; nt < 4; nt++) {
                int f = ((kc * 2 + ks) * 16 + warp_n * 4 + nt) * WFRAG;
                *(float2*)bhi[nt] = *(const float2*)&Whi[f + lane * 2];
                *(float2*)blo[nt] = *(const float2*)&Wlo[f + lane * 2];
            }
#pragma unroll
            for (int mt = 0; mt < 2; mt++)
#pragma unroll
                for (int nt = 0; nt < 4; nt++) {
                    mma_tf32(acc[mt][nt], ahi[mt], blo[nt]);
                    mma_tf32(acc[mt][nt], alo[mt], bhi[nt]);
                    mma_tf32(acc[mt][nt], ahi[mt], bhi[nt]);
                }
        }

        if (kc < 7) store_x(xnext, buf ^ 1);
        __syncthreads();
        buf ^= 1;
    }

    // ---- store result ----
    int g  = lane >> 2;
    int tg = lane & 3;
#pragma unroll
    for (int mt = 0; mt < 2; mt++)
#pragma unroll
        for (int nt = 0; nt < 4; nt++) {
            int r = row0 + warp_m * 32 + mt * 16 + g;
            int c = warp_n * 32 + nt * 8 + tg * 2;
            if (r < n)
                *(float2*)(g_t + (size_t)r * DH + c) =
                    make_float2(acc[mt][nt][0], acc[mt][nt][1]);
            if (r + 8 < n)
                *(float2*)(g_t + (size_t)(r + 8) * DH + c) =
                    make_float2(acc[mt][nt][2], acc[mt][nt][3]);
        }
}

// ---------------- GEMM 128x40 (input = g_h with fused BN+ReLU), writes g_t[n,40] ----------------
__global__ void __launch_bounds__(240) gemm40(const float* __restrict__ W, int n) {
    __shared__ float ws[DH * DOUT];
    __shared__ float xs[48][32];

    int tx  = threadIdx.x;
    int ty  = threadIdx.y;
    int tid = ty * 40 + tx;

    for (int i = tid; i < DH * DOUT; i += 240) ws[i] = W[i];

    int row0 = blockIdx.x * 48;
    float acc[8];
#pragma unroll
    for (int r = 0; r < 8; r++) acc[r] = 0.f;

    for (int kc = 0; kc < 4; kc++) {
        for (int i = tid; i < 384; i += 240) {
            int r  = i >> 3;
            int c4 = i & 7;
            int gr = row0 + r;
            float4 v = make_float4(0.f, 0.f, 0.f, 0.f);
            if (gr < n) v = *(const float4*)(g_h + (size_t)gr * DH + kc * 32 + c4 * 4);
            float4 sc = *(const float4*)(g_scale + kc * 32 + c4 * 4);
            float4 sh = *(const float4*)(g_shift + kc * 32 + c4 * 4);
            v.x = fmaxf(0.f, fmaf(v.x, sc.x, sh.x));
            v.y = fmaxf(0.f, fmaf(v.y, sc.y, sh.y));
            v.z = fmaxf(0.f, fmaf(v.z, sc.z, sh.z));
            v.w = fmaxf(0.f, fmaf(v.w, sc.w, sh.w));
            *(float4*)&xs[r][c4 * 4] = v;
        }
        __syncthreads();
#pragma unroll
        for (int kk = 0; kk < 32; kk++) {
            float wv = ws[(kc * 32 + kk) * DOUT + tx];
#pragma unroll
            for (int r8 = 0; r8 < 8; r8++)
                acc[r8] = fmaf(xs[ty * 8 + r8][kk], wv, acc[r8]);
        }
        __syncthreads();
    }
#pragma unroll
    for (int r8 = 0; r8 < 8; r8++) {
        int gr = row0 + ty * 8 + r8;
        if (gr < n) g_t[(size_t)gr * DOUT + tx] = acc[r8];
    }
}

// ---------------- fused aggregate + combine + BN stats, F=128. One warp per row. ----------------
__global__ void __launch_bounds__(256) agg_combine128(const float* __restrict__ b, int n) {
    int lane = threadIdx.x & 31;
    int wip  = threadIdx.x >> 5;
    const float4* T = (const float4*)g_t;
    float4 bc = ((const float4*)b)[lane];

    float4 ssum = make_float4(0.f, 0.f, 0.f, 0.f);
    float4 ssq  = make_float4(0.f, 0.f, 0.f, 0.f);

    for (int row = blockIdx.x * 8 + wip; row < n; row += gridDim.x * 8) {
        int start = g_rowstart[row];
        int cnt   = g_deg[row];
        float4 acc = make_float4(0.f, 0.f, 0.f, 0.f);
        for (int j = start; j < start + cnt; j++) {
            int2  pr = g_csr[j];
            float w  = __int_as_float(pr.y);
            float4 v = __ldg(T + (size_t)pr.x * 32 + lane);
            acc.x = fmaf(w, v.x, acc.x);
            acc.y = fmaf(w, v.y, acc.y);
            acc.z = fmaf(w, v.z, acc.z);
            acc.w = fmaf(w, v.w, acc.w);
        }
        float dq = g_disq[row];
        float sn = dq * dq;
        float4 t = __ldg(T + (size_t)row * 32 + lane);
        float4 h;
        h.x = fmaf(sn, t.x, acc.x) + bc.x;
        h.y = fmaf(sn, t.y, acc.y) + bc.y;
        h.z = fmaf(sn, t.z, acc.z) + bc.z;
        h.w = fmaf(sn, t.w, acc.w) + bc.w;
        ((float4*)g_h)[(size_t)row * 32 + lane] = h;
        ssum.x += h.x; ssum.y += h.y; ssum.z += h.z; ssum.w += h.w;
        ssq.x = fmaf(h.x, h.x, ssq.x); ssq.y = fmaf(h.y, h.y, ssq.y);
        ssq.z = fmaf(h.z, h.z, ssq.z); ssq.w = fmaf(h.w, h.w, ssq.w);
    }

    __shared__ float4 sh1[8][32];
    __shared__ float4 sh2[8][32];
    sh1[wip][lane] = ssum;
    sh2[wip][lane] = ssq;
    __syncthreads();
    if (wip == 0) {
        float4 a = sh1[0][lane], q = sh2[0][lane];
#pragma unroll
        for (int w = 1; w < 8; w++) {
            float4 a2 = sh1[w][lane], q2 = sh2[w][lane];
            a.x += a2.x; a.y += a2.y; a.z += a2.z; a.w += a2.w;
            q.x += q2.x; q.y += q2.y; q.z += q2.z; q.w += q2.w;
        }
        red_add_v4(g_stats + lane * 4, a);
        red_add_v4(g_stats + DH + lane * 4, q);
    }
}

// ---------------- BN finalize ----------------
__global__ void bn_finalize(const float* __restrict__ gam, const float* __restrict__ bet, int n) {
    int c = threadIdx.x;
    if (c < DH) {
        float inv_n = 1.0f / (float)n;
        float mu  = g_stats[c] * inv_n;
        float var = g_stats[DH + c] * inv_n - mu * mu;
        float rs  = rsqrtf(var + BN_EPS);
        float sc  = rs * gam[c];
        g_scale[c] = sc;
        g_shift[c] = bet[c] - mu * sc;
    }
}

// ---------------- fused aggregate + combine + log_softmax, F=40. One warp per row. ----------------
__global__ void __launch_bounds__(256) agg40_lsm(const float* __restrict__ b2,
                                                 float* __restrict__ out, int n) {
    int lane = threadIdx.x & 31;
    int wip  = threadIdx.x >> 5;
    const float4* T = (const float4*)g_t;
    bool active = (lane < 10);
    float4 bc = make_float4(0.f, 0.f, 0.f, 0.f);
    if (active) bc = ((const float4*)b2)[lane];

    for (int row = blockIdx.x * 8 + wip; row < n; row += gridDim.x * 8) {
        int start = g_rowstart[row];
        int cnt   = g_deg[row];
        float4 acc = make_float4(0.f, 0.f, 0.f, 0.f);
        for (int j = start; j < start + cnt; j++) {
            int2  pr = g_csr[j];
            float w  = __int_as_float(pr.y);
            if (active) {
                float4 v = __ldg(T + (size_t)pr.x * 10 + lane);
                acc.x = fmaf(w, v.x, acc.x);
                acc.y = fmaf(w, v.y, acc.y);
                acc.z = fmaf(w, v.z, acc.z);
                acc.w = fmaf(w, v.w, acc.w);
            }
        }
        float dq = g_disq[row];
        float sn = dq * dq;
        float4 h = make_float4(-1e30f, -1e30f, -1e30f, -1e30f);
        if (active) {
            float4 t = __ldg(T + (size_t)row * 10 + lane);
            h.x = fmaf(sn, t.x, acc.x) + bc.x;
            h.y = fmaf(sn, t.y, acc.y) + bc.y;
            h.z = fmaf(sn, t.z, acc.z) + bc.z;
            h.w = fmaf(sn, t.w, acc.w) + bc.w;
        }
        float m = fmaxf(fmaxf(h.x, h.y), fmaxf(h.z, h.w));
#pragma unroll
        for (int o = 16; o; o >>= 1) m = fmaxf(m, __shfl_xor_sync(0xFFFFFFFFu, m, o));
        float se = 0.f;
        if (active)
            se = expf(h.x - m) + expf(h.y - m) + expf(h.z - m) + expf(h.w - m);
#pragma unroll
        for (int o = 16; o; o >>= 1) se += __shfl_xor_sync(0xFFFFFFFFu, se, o);
        float lse = m + logf(se);
        if (active) {
            float4 r = make_float4(h.x - lse, h.y - lse, h.z - lse, h.w - lse);
            ((float4*)out)[(size_t)row * 10 + lane] = r;
        }
    }
}

// ---------------- launch ----------------
extern "C" void kernel_launch(void* const* d_in, const int* in_sizes, int n_in,
                              void* d_out, int out_size) {
    const float* x   = (const float*)d_in[0];
    const int*   src = (const int*)d_in[1];
    const int*   dst = (const int*)d_in[2];
    const float* W0  = (const float*)d_in[3];
    const float* b0  = (const float*)d_in[4];
    const float* W1  = (const float*)d_in[5];
    const float* b1  = (const float*)d_in[6];
    const float* W2  = (const float*)d_in[7];
    const float* b2  = (const float*)d_in[8];
    const float* g0  = (const float*)d_in[9];
    const float* be0 = (const float*)d_in[10];
    const float* g1  = (const float*)d_in[11];
    const float* be1 = (const float*)d_in[12];
    float* out = (float*)d_out;

    int n = in_sizes[0] / DH;
    int e = in_sizes[1];
    int nb = (n + SCAN_B - 1) / SCAN_B;

    int agg_blocks  = 1480;
    int gemm_blocks = (n + 127) / 128;

    cudaFuncSetAttribute(gemm128_tc, cudaFuncAttributeMaxDynamicSharedMemorySize,
                         GEMM_SMEM_BYTES);

    // ---- CSR build (layer-0 GEMM interleaved; independent of CSR) ----
    zero_deg<<<(n + 255) / 256, 256>>>(n);
    count_deg<<<(e + 255) / 256, 256>>>(dst, e);
    calc_disq<<<(n + 255) / 256, 256>>>(n);
    gemm128_tc<<<gemm_blocks, 512, GEMM_SMEM_BYTES>>>(x, W0, n, 0);
    scan1<<<nb, SCAN_B>>>(n);
    scan2<<<1, NB_MAX>>>(nb);
    scan3<<<(n + 255) / 256, 256>>>(n);
    fill_csr<<<(e + 255) / 256, 256>>>(src, dst, e);

    // ---- layer 0 (agg part) ----
    zero_stats<<<1, 256>>>();
    agg_combine128<<<agg_blocks, 256>>>(b0, n);
    bn_finalize<<<1, DH>>>(g0, be0, n);

    // ---- layer 1 ----
    gemm128_tc<<<gemm_blocks, 512, GEMM_SMEM_BYTES>>>(nullptr, W1, n, 1);
    zero_stats<<<1, 256>>>();
    agg_combine128<<<agg_blocks, 256>>>(b1, n);
    bn_finalize<<<1, DH>>>(g1, be1, n);

    // ---- layer 2 ----
    gemm40<<<(n + 47) / 48, dim3(DOUT, 6)>>>(W2, n);
    agg40_lsm<<<agg_blocks, 256>>>(b2, out, n);
}

// round 8
// speedup vs baseline: 1.1084x; 1.0503x over previous
#include <cuda_runtime.h>
#include <math.h>

#define N_MAX 100000
#define E_MAX 1600000
#define DH 128
#define DOUT 40
#define BN_EPS 1e-5f
#define SCAN_B 1024
#define NB_MAX 128   // ceil(N_MAX/1024) = 98

// ---------------- scratch (static device globals; no allocation) ----------------
__device__ int   g_deg[N_MAX];
__device__ int   g_incl[N_MAX];
__device__ int   g_bsum[NB_MAX];
__device__ int   g_bscan[NB_MAX];
__device__ int   g_rowstart[N_MAX];
__device__ int   g_cursor[N_MAX];
__device__ float g_disq[N_MAX];
__device__ int2  g_csr[E_MAX];
__device__ float g_t[(size_t)N_MAX * DH];
__device__ float g_h[(size_t)N_MAX * DH];
__device__ float g_stats[2 * DH];
__device__ float g_scale[DH];
__device__ float g_shift[DH];

// ---------------- helpers ----------------
__device__ __forceinline__ void red_add_v4(float* p, float4 v) {
    asm volatile("red.global.add.v4.f32 [%0], {%1,%2,%3,%4};"
                 :: "l"(p), "f"(v.x), "f"(v.y), "f"(v.z), "f"(v.w) : "memory");
}
// cvt.rna.tf32.f32 needs a .b32 (integer) destination register.
__device__ __forceinline__ float tf32_rn(float f) {
    unsigned r;
    asm("cvt.rna.tf32.f32 %0, %1;" : "=r"(r) : "f"(f));
    return __int_as_float((int)r);
}
__device__ __forceinline__ void mma_tf32(float* d, const float* a, const float* b) {
    asm volatile(
        "mma.sync.aligned.m16n8k8.row.col.f32.tf32.tf32.f32 "
        "{%0,%1,%2,%3}, {%4,%5,%6,%7}, {%8,%9}, {%0,%1,%2,%3};\n"
        : "+f"(d[0]), "+f"(d[1]), "+f"(d[2]), "+f"(d[3])
        : "r"(__float_as_int(a[0])), "r"(__float_as_int(a[1])),
          "r"(__float_as_int(a[2])), "r"(__float_as_int(a[3])),
          "r"(__float_as_int(b[0])), "r"(__float_as_int(b[1])));
}

// ---------------- CSR build ----------------
__global__ void zero_deg(int n) {
    int i = blockIdx.x * blockDim.x + threadIdx.x;
    if (i < n) g_deg[i] = 0;
}
__global__ void count_deg(const int* __restrict__ dst, int e) {
    int i = blockIdx.x * blockDim.x + threadIdx.x;
    if (i < e) atomicAdd(&g_deg[dst[i]], 1);
}
__global__ void calc_disq(int n) {
    int i = blockIdx.x * blockDim.x + threadIdx.x;
    if (i < n) g_disq[i] = rsqrtf(1.0f + (float)g_deg[i]);
}
__global__ void scan1(int n) {
    __shared__ int sm[SCAN_B];
    int tid = threadIdx.x;
    int i = blockIdx.x * SCAN_B + tid;
    sm[tid] = (i < n) ? g_deg[i] : 0;
    __syncthreads();
#pragma unroll
    for (int off = 1; off < SCAN_B; off <<= 1) {
        int t = (tid >= off) ? sm[tid - off] : 0;
        __syncthreads();
        sm[tid] += t;
        __syncthreads();
    }
    if (i < n) g_incl[i] = sm[tid];
    if (tid == SCAN_B - 1) g_bsum[blockIdx.x] = sm[tid];
}
__global__ void scan2(int nb) {
    __shared__ int sm[NB_MAX];
    int tid = threadIdx.x;
    sm[tid] = (tid < nb) ? g_bsum[tid] : 0;
    __syncthreads();
#pragma unroll
    for (int off = 1; off < NB_MAX; off <<= 1) {
        int t = (tid >= off) ? sm[tid - off] : 0;
        __syncthreads();
        sm[tid] += t;
        __syncthreads();
    }
    if (tid < nb) g_bscan[tid] = sm[tid];
}
__global__ void scan3(int n) {
    int i = blockIdx.x * blockDim.x + threadIdx.x;
    if (i < n) {
        int b = i / SCAN_B;
        int base = (b > 0) ? g_bscan[b - 1] : 0;
        int rs = base + g_incl[i] - g_deg[i];
        g_rowstart[i] = rs;
        g_cursor[i]   = rs;
    }
}
__global__ void fill_csr(const int* __restrict__ src, const int* __restrict__ dst, int e) {
    int i = blockIdx.x * blockDim.x + threadIdx.x;
    if (i < e) {
        int s = src[i], d = dst[i];
        int pos = atomicAdd(&g_cursor[d], 1);
        float w = g_disq[s] * g_disq[d];
        g_csr[pos] = make_int2(s, __float_as_int(w));
    }
}
__global__ void zero_stats() {
    int i = threadIdx.x;
    if (i < 2 * DH) g_stats[i] = 0.0f;
}

// ============ GEMM 128x128 via 3xTF32 tensor cores ============
// 256 threads (8 warps: 2 m x 4 n), warp tile 64x32, block tile 128x128, BK=16.
// Fragment-major smem holds raw fp32; hi/lo tf32 split done in registers at consume.
// Both X and W double-buffered per K-chunk; one __syncthreads per chunk; 2 CTAs/SM.
//
// A-frag (m16k8): lane L (g=L>>2, tg=L&3) holds {X[g][tg], X[g+8][tg], X[g][tg+4], X[g+8][tg+4]}
//   frag = 32 lanes * float4 = 128 words, padded to 132.
// B-frag (k8n8):  lane L holds {W[tg][g], W[tg+4][g]} -> 64 words, padded to 66.
#define XFRAG 132
#define WFRAG 66
#define XWORDS (16 * XFRAG)   // 8 tm x 2 ks frags = 2112 words
#define WWORDS (32 * WFRAG)   // 2 ks x 16 nt frags = 2112 words

__global__ void __launch_bounds__(256, 2) gemm128_tc(const float* __restrict__ Xin,
                                                     const float* __restrict__ W,
                                                     int n, int use_bn) {
    __shared__ float Xs[2][XWORDS];
    __shared__ float Ws[2][WWORDS];

    const float* X = Xin ? Xin : g_h;
    int tid  = threadIdx.x;
    int lane = tid & 31;
    int wid  = tid >> 5;
    int warp_m = wid & 1;     // 2 m-halves of 64 rows
    int warp_n = wid >> 1;    // 4 n-quarters of 32 cols
    int row0 = blockIdx.x * 128;

    // ---- producer helpers ----
    auto load_x4 = [&](int kc, int q) -> float4 {
        int xr = q >> 2, xc4 = q & 3;
        int gr = row0 + xr;
        float4 v = make_float4(0.f, 0.f, 0.f, 0.f);
        if (gr < n) v = *(const float4*)(X + (size_t)gr * DH + kc * 16 + xc4 * 4);
        if (use_bn) {
            float4 sc = *(const float4*)(g_scale + kc * 16 + xc4 * 4);
            float4 sh = *(const float4*)(g_shift + kc * 16 + xc4 * 4);
            v.x = fmaxf(0.f, fmaf(v.x, sc.x, sh.x));
            v.y = fmaxf(0.f, fmaf(v.y, sc.y, sh.y));
            v.z = fmaxf(0.f, fmaf(v.z, sc.z, sh.z));
            v.w = fmaxf(0.f, fmaf(v.w, sc.w, sh.w));
        }
        return v;
    };
    auto store_x4 = [&](float4 v, int q, int buf) {
        int xr = q >> 2, xc4 = q & 3;
        int tm = xr >> 4, ri = xr & 15, ks = xc4 >> 1;
        int slot = (ri >> 3) + 2 * (xc4 & 1);
        int lb   = (ri & 7) * 4;
        float* base = &Xs[buf][(tm * 2 + ks) * XFRAG + slot];
        base[(lb + 0) * 4] = v.x;
        base[(lb + 1) * 4] = v.y;
        base[(lb + 2) * 4] = v.z;
        base[(lb + 3) * 4] = v.w;
    };
    auto load_w4 = [&](int kc, int q) -> float4 {
        int kl = q >> 5, c4 = q & 31;
        return *(const float4*)(W + (size_t)(kc * 16 + kl) * DH + c4 * 4);
    };
    auto store_w4 = [&](float4 v, int q, int buf) {
        int kl = q >> 5, c4 = q & 31;
        int ks = (kl >> 3) & 1, slot = (kl >> 2) & 1, kj = kl & 3;
        int nt = c4 >> 1;
        int lb = 16 * (c4 & 1) + kj;   // lane for j=0; lane_j = lb + 4j
        float* base = &Ws[buf][(ks * 16 + nt) * WFRAG + slot];
        base[(lb + 0)  * 2] = v.x;
        base[(lb + 4)  * 2] = v.y;
        base[(lb + 8)  * 2] = v.z;
        base[(lb + 12) * 2] = v.w;
    };

    float acc[4][4][4];
#pragma unroll
    for (int mt = 0; mt < 4; mt++)
#pragma unroll
        for (int nt = 0; nt < 4; nt++)
#pragma unroll
            for (int k = 0; k < 4; k++) acc[mt][nt][k] = 0.f;

    // ---- prologue: stage chunk 0 ----
    store_x4(load_x4(0, tid), tid, 0);
    store_x4(load_x4(0, tid + 256), tid + 256, 0);
    store_w4(load_w4(0, tid), tid, 0);
    store_w4(load_w4(0, tid + 256), tid + 256, 0);
    __syncthreads();

    int buf = 0;
    for (int kc = 0; kc < 8; kc++) {
        float4 px0, px1, pw0, pw1;
        if (kc < 7) {
            px0 = load_x4(kc + 1, tid);
            px1 = load_x4(kc + 1, tid + 256);
            pw0 = load_w4(kc + 1, tid);
            pw1 = load_w4(kc + 1, tid + 256);
        }

#pragma unroll
        for (int ks = 0; ks < 2; ks++) {
            // B fragments: raw fp32 load + in-register 3xTF32 split
            float bhi[4][2], blo[4][2];
#pragma unroll
            for (int nt = 0; nt < 4; nt++) {
                const float2 bv = *(const float2*)
                    &Ws[buf][(ks * 16 + warp_n * 4 + nt) * WFRAG + lane * 2];
                bhi[nt][0] = tf32_rn(bv.x); blo[nt][0] = tf32_rn(bv.x - bhi[nt][0]);
                bhi[nt][1] = tf32_rn(bv.y); blo[nt][1] = tf32_rn(bv.y - bhi[nt][1]);
            }
#pragma unroll
            for (int mt = 0; mt < 4; mt++) {
                const float4 av = *(const float4*)
                    &Xs[buf][((warp_m * 4 + mt) * 2 + ks) * XFRAG + lane * 4];
                float ahi[4], alo[4];
                ahi[0] = tf32_rn(av.x); alo[0] = tf32_rn(av.x - ahi[0]);
                ahi[1] = tf32_rn(av.y); alo[1] = tf32_rn(av.y - ahi[1]);
                ahi[2] = tf32_rn(av.z); alo[2] = tf32_rn(av.z - ahi[2]);
                ahi[3] = tf32_rn(av.w); alo[3] = tf32_rn(av.w - ahi[3]);
#pragma unroll
                for (int nt = 0; nt < 4; nt++) {
                    mma_tf32(acc[mt][nt], ahi, blo[nt]);
                    mma_tf32(acc[mt][nt], alo, bhi[nt]);
                    mma_tf32(acc[mt][nt], ahi, bhi[nt]);
                }
            }
        }

        if (kc < 7) {
            store_x4(px0, tid, buf ^ 1);
            store_x4(px1, tid + 256, buf ^ 1);
            store_w4(pw0, tid, buf ^ 1);
            store_w4(pw1, tid + 256, buf ^ 1);
        }
        __syncthreads();
        buf ^= 1;
    }

    // ---- store result ----
    int g  = lane >> 2;
    int tg = lane & 3;
#pragma unroll
    for (int mt = 0; mt < 4; mt++)
#pragma unroll
        for (int nt = 0; nt < 4; nt++) {
            int r = row0 + warp_m * 64 + mt * 16 + g;
            int c = warp_n * 32 + nt * 8 + tg * 2;
            if (r < n)
                *(float2*)(g_t + (size_t)r * DH + c) =
                    make_float2(acc[mt][nt][0], acc[mt][nt][1]);
            if (r + 8 < n)
                *(float2*)(g_t + (size_t)(r + 8) * DH + c) =
                    make_float2(acc[mt][nt][2], acc[mt][nt][3]);
        }
}

// ---------------- GEMM 128x40 (input = g_h with fused BN+ReLU), writes g_t[n,40] ----------------
__global__ void __launch_bounds__(240) gemm40(const float* __restrict__ W, int n) {
    __shared__ float ws[DH * DOUT];
    __shared__ float xs[48][32];

    int tx  = threadIdx.x;
    int ty  = threadIdx.y;
    int tid = ty * 40 + tx;

    for (int i = tid; i < DH * DOUT; i += 240) ws[i] = W[i];

    int row0 = blockIdx.x * 48;
    float acc[8];
#pragma unroll
    for (int r = 0; r < 8; r++) acc[r] = 0.f;

    for (int kc = 0; kc < 4; kc++) {
        for (int i = tid; i < 384; i += 240) {
            int r  = i >> 3;
            int c4 = i & 7;
            int gr = row0 + r;
            float4 v = make_float4(0.f, 0.f, 0.f, 0.f);
            if (gr < n) v = *(const float4*)(g_h + (size_t)gr * DH + kc * 32 + c4 * 4);
            float4 sc = *(const float4*)(g_scale + kc * 32 + c4 * 4);
            float4 sh = *(const float4*)(g_shift + kc * 32 + c4 * 4);
            v.x = fmaxf(0.f, fmaf(v.x, sc.x, sh.x));
            v.y = fmaxf(0.f, fmaf(v.y, sc.y, sh.y));
            v.z = fmaxf(0.f, fmaf(v.z, sc.z, sh.z));
            v.w = fmaxf(0.f, fmaf(v.w, sc.w, sh.w));
            *(float4*)&xs[r][c4 * 4] = v;
        }
        __syncthreads();
#pragma unroll
        for (int kk = 0; kk < 32; kk++) {
            float wv = ws[(kc * 32 + kk) * DOUT + tx];
#pragma unroll
            for (int r8 = 0; r8 < 8; r8++)
                acc[r8] = fmaf(xs[ty * 8 + r8][kk], wv, acc[r8]);
        }
        __syncthreads();
    }
#pragma unroll
    for (int r8 = 0; r8 < 8; r8++) {
        int gr = row0 + ty * 8 + r8;
        if (gr < n) g_t[(size_t)gr * DOUT + tx] = acc[r8];
    }
}

// ---------------- fused aggregate + combine + BN stats, F=128. One warp per row. ----------------
__global__ void __launch_bounds__(256) agg_combine128(const float* __restrict__ b, int n) {
    int lane = threadIdx.x & 31;
    int wip  = threadIdx.x >> 5;
    const float4* T = (const float4*)g_t;
    float4 bc = ((const float4*)b)[lane];

    float4 ssum = make_float4(0.f, 0.f, 0.f, 0.f);
    float4 ssq  = make_float4(0.f, 0.f, 0.f, 0.f);

    for (int row = blockIdx.x * 8 + wip; row < n; row += gridDim.x * 8) {
        int start = g_rowstart[row];
        int cnt   = g_deg[row];
        float4 acc = make_float4(0.f, 0.f, 0.f, 0.f);
        for (int j = start; j < start + cnt; j++) {
            int2  pr = g_csr[j];
            float w  = __int_as_float(pr.y);
            float4 v = __ldg(T + (size_t)pr.x * 32 + lane);
            acc.x = fmaf(w, v.x, acc.x);
            acc.y = fmaf(w, v.y, acc.y);
            acc.z = fmaf(w, v.z, acc.z);
            acc.w = fmaf(w, v.w, acc.w);
        }
        float dq = g_disq[row];
        float sn = dq * dq;
        float4 t = __ldg(T + (size_t)row * 32 + lane);
        float4 h;
        h.x = fmaf(sn, t.x, acc.x) + bc.x;
        h.y = fmaf(sn, t.y, acc.y) + bc.y;
        h.z = fmaf(sn, t.z, acc.z) + bc.z;
        h.w = fmaf(sn, t.w, acc.w) + bc.w;
        ((float4*)g_h)[(size_t)row * 32 + lane] = h;
        ssum.x += h.x; ssum.y += h.y; ssum.z += h.z; ssum.w += h.w;
        ssq.x = fmaf(h.x, h.x, ssq.x); ssq.y = fmaf(h.y, h.y, ssq.y);
        ssq.z = fmaf(h.z, h.z, ssq.z); ssq.w = fmaf(h.w, h.w, ssq.w);
    }

    __shared__ float4 sh1[8][32];
    __shared__ float4 sh2[8][32];
    sh1[wip][lane] = ssum;
    sh2[wip][lane] = ssq;
    __syncthreads();
    if (wip == 0) {
        float4 a = sh1[0][lane], q = sh2[0][lane];
#pragma unroll
        for (int w = 1; w < 8; w++) {
            float4 a2 = sh1[w][lane], q2 = sh2[w][lane];
            a.x += a2.x; a.y += a2.y; a.z += a2.z; a.w += a2.w;
            q.x += q2.x; q.y += q2.y; q.z += q2.z; q.w += q2.w;
        }
        red_add_v4(g_stats + lane * 4, a);
        red_add_v4(g_stats + DH + lane * 4, q);
    }
}

// ---------------- BN finalize ----------------
__global__ void bn_finalize(const float* __restrict__ gam, const float* __restrict__ bet, int n) {
    int c = threadIdx.x;
    if (c < DH) {
        float inv_n = 1.0f / (float)n;
        float mu  = g_stats[c] * inv_n;
        float var = g_stats[DH + c] * inv_n - mu * mu;
        float rs  = rsqrtf(var + BN_EPS);
        float sc  = rs * gam[c];
        g_scale[c] = sc;
        g_shift[c] = bet[c] - mu * sc;
    }
}

// ---------------- fused aggregate + combine + log_softmax, F=40. One warp per row. ----------------
__global__ void __launch_bounds__(256) agg40_lsm(const float* __restrict__ b2,
                                                 float* __restrict__ out, int n) {
    int lane = threadIdx.x & 31;
    int wip  = threadIdx.x >> 5;
    const float4* T = (const float4*)g_t;
    bool active = (lane < 10);
    float4 bc = make_float4(0.f, 0.f, 0.f, 0.f);
    if (active) bc = ((const float4*)b2)[lane];

    for (int row = blockIdx.x * 8 + wip; row < n; row += gridDim.x * 8) {
        int start = g_rowstart[row];
        int cnt   = g_deg[row];
        float4 acc = make_float4(0.f, 0.f, 0.f, 0.f);
        for (int j = start; j < start + cnt; j++) {
            int2  pr = g_csr[j];
            float w  = __int_as_float(pr.y);
            if (active) {
                float4 v = __ldg(T + (size_t)pr.x * 10 + lane);
                acc.x = fmaf(w, v.x, acc.x);
                acc.y = fmaf(w, v.y, acc.y);
                acc.z = fmaf(w, v.z, acc.z);
                acc.w = fmaf(w, v.w, acc.w);
            }
        }
        float dq = g_disq[row];
        float sn = dq * dq;
        float4 h = make_float4(-1e30f, -1e30f, -1e30f, -1e30f);
        if (active) {
            float4 t = __ldg(T + (size_t)row * 10 + lane);
            h.x = fmaf(sn, t.x, acc.x) + bc.x;
            h.y = fmaf(sn, t.y, acc.y) + bc.y;
            h.z = fmaf(sn, t.z, acc.z) + bc.z;
            h.w = fmaf(sn, t.w, acc.w) + bc.w;
        }
        float m = fmaxf(fmaxf(h.x, h.y), fmaxf(h.z, h.w));
#pragma unroll
        for (int o = 16; o; o >>= 1) m = fmaxf(m, __shfl_xor_sync(0xFFFFFFFFu, m, o));
        float se = 0.f;
        if (active)
            se = expf(h.x - m) + expf(h.y - m) + expf(h.z - m) + expf(h.w - m);
#pragma unroll
        for (int o = 16; o; o >>= 1) se += __shfl_xor_sync(0xFFFFFFFFu, se, o);
        float lse = m + logf(se);
        if (active) {
            float4 r = make_float4(h.x - lse, h.y - lse, h.z - lse, h.w - lse);
            ((float4*)out)[(size_t)row * 10 + lane] = r;
        }
    }
}

// ---------------- launch ----------------
extern "C" void kernel_launch(void* const* d_in, const int* in_sizes, int n_in,
                              void* d_out, int out_size) {
    const float* x   = (const float*)d_in[0];
    const int*   src = (const int*)d_in[1];
    const int*   dst = (const int*)d_in[2];
    const float* W0  = (const float*)d_in[3];
    const float* b0  = (const float*)d_in[4];
    const float* W1  = (const float*)d_in[5];
    const float* b1  = (const float*)d_in[6];
    const float* W2  = (const float*)d_in[7];
    const float* b2  = (const float*)d_in[8];
    const float* g0  = (const float*)d_in[9];
    const float* be0 = (const float*)d_in[10];
    const float* g1  = (const float*)d_in[11];
    const float* be1 = (const float*)d_in[12];
    float* out = (float*)d_out;

    int n = in_sizes[0] / DH;
    int e = in_sizes[1];
    int nb = (n + SCAN_B - 1) / SCAN_B;

    int agg_blocks  = 1480;
    int gemm_blocks = (n + 127) / 128;

    // ---- CSR build (layer-0 GEMM interleaved at launch index 3 for profiling) ----
    zero_deg<<<(n + 255) / 256, 256>>>(n);
    count_deg<<<(e + 255) / 256, 256>>>(dst, e);
    calc_disq<<<(n + 255) / 256, 256>>>(n);
    gemm128_tc<<<gemm_blocks, 256>>>(x, W0, n, 0);
    scan1<<<nb, SCAN_B>>>(n);
    scan2<<<1, NB_MAX>>>(nb);
    scan3<<<(n + 255) / 256, 256>>>(n);
    fill_csr<<<(e + 255) / 256, 256>>>(src, dst, e);

    // ---- layer 0 (agg part) ----
    zero_stats<<<1, 256>>>();
    agg_combine128<<<agg_blocks, 256>>>(b0, n);
    bn_finalize<<<1, DH>>>(g0, be0, n);

    // ---- layer 1 ----
    gemm128_tc<<<gemm_blocks, 256>>>(nullptr, W1, n, 1);
    zero_stats<<<1, 256>>>();
    agg_combine128<<<agg_blocks, 256>>>(b1, n);
    bn_finalize<<<1, DH>>>(g1, be1, n);

    // ---- layer 2 ----
    gemm40<<<(n + 47) / 48, dim3(DOUT, 6)>>>(W2, n);
    agg40_lsm<<<agg_blocks, 256>>>(b2, out, n);
}

// round 9
// speedup vs baseline: 1.1314x; 1.0208x over previous
#include <cuda_runtime.h>
#include <math.h>

#define N_MAX 100000
#define E_MAX 1600000
#define DH 128
#define DOUT 40
#define BN_EPS 1e-5f
#define SCAN_B 1024
#define NB_MAX 128   // ceil(N_MAX/1024) = 98

// ---------------- scratch (static device globals; no allocation) ----------------
__device__ int   g_deg[N_MAX];
__device__ int   g_incl[N_MAX];
__device__ int   g_bsum[NB_MAX];
__device__ int   g_bscan[NB_MAX];
__device__ int   g_rowstart[N_MAX];
__device__ int   g_cursor[N_MAX];
__device__ float g_disq[N_MAX];
__device__ int2  g_csr[E_MAX];
__device__ float g_t[(size_t)N_MAX * DH];
__device__ float g_h[(size_t)N_MAX * DH];
__device__ float g_stats[2 * DH];
__device__ float g_scale[DH];
__device__ float g_shift[DH];

// ---------------- helpers ----------------
__device__ __forceinline__ void red_add_v4(float* p, float4 v) {
    asm volatile("red.global.add.v4.f32 [%0], {%1,%2,%3,%4};"
                 :: "l"(p), "f"(v.x), "f"(v.y), "f"(v.z), "f"(v.w) : "memory");
}
// cvt.rna.tf32.f32 needs a .b32 (integer) destination register.
__device__ __forceinline__ float tf32_rn(float f) {
    unsigned r;
    asm("cvt.rna.tf32.f32 %0, %1;" : "=r"(r) : "f"(f));
    return __int_as_float((int)r);
}
__device__ __forceinline__ void mma_tf32(float* d, const float* a, const float* b) {
    asm volatile(
        "mma.sync.aligned.m16n8k8.row.col.f32.tf32.tf32.f32 "
        "{%0,%1,%2,%3}, {%4,%5,%6,%7}, {%8,%9}, {%0,%1,%2,%3};\n"
        : "+f"(d[0]), "+f"(d[1]), "+f"(d[2]), "+f"(d[3])
        : "r"(__float_as_int(a[0])), "r"(__float_as_int(a[1])),
          "r"(__float_as_int(a[2])), "r"(__float_as_int(a[3])),
          "r"(__float_as_int(b[0])), "r"(__float_as_int(b[1])));
}

// ---------------- CSR build ----------------
__global__ void zero_deg(int n) {
    int i = blockIdx.x * blockDim.x + threadIdx.x;
    if (i < n) g_deg[i] = 0;
}
__global__ void count_deg(const int* __restrict__ dst, int e) {
    int i = blockIdx.x * blockDim.x + threadIdx.x;
    if (i < e) atomicAdd(&g_deg[dst[i]], 1);
}
__global__ void calc_disq(int n) {
    int i = blockIdx.x * blockDim.x + threadIdx.x;
    if (i < n) g_disq[i] = rsqrtf(1.0f + (float)g_deg[i]);
}
__global__ void scan1(int n) {
    __shared__ int sm[SCAN_B];
    int tid = threadIdx.x;
    int i = blockIdx.x * SCAN_B + tid;
    sm[tid] = (i < n) ? g_deg[i] : 0;
    __syncthreads();
#pragma unroll
    for (int off = 1; off < SCAN_B; off <<= 1) {
        int t = (tid >= off) ? sm[tid - off] : 0;
        __syncthreads();
        sm[tid] += t;
        __syncthreads();
    }
    if (i < n) g_incl[i] = sm[tid];
    if (tid == SCAN_B - 1) g_bsum[blockIdx.x] = sm[tid];
}
__global__ void scan2(int nb) {
    __shared__ int sm[NB_MAX];
    int tid = threadIdx.x;
    sm[tid] = (tid < nb) ? g_bsum[tid] : 0;
    __syncthreads();
#pragma unroll
    for (int off = 1; off < NB_MAX; off <<= 1) {
        int t = (tid >= off) ? sm[tid - off] : 0;
        __syncthreads();
        sm[tid] += t;
        __syncthreads();
    }
    if (tid < nb) g_bscan[tid] = sm[tid];
}
__global__ void scan3(int n) {
    int i = blockIdx.x * blockDim.x + threadIdx.x;
    if (i < n) {
        int b = i / SCAN_B;
        int base = (b > 0) ? g_bscan[b - 1] : 0;
        int rs = base + g_incl[i] - g_deg[i];
        g_rowstart[i] = rs;
        g_cursor[i]   = rs;
    }
}
__global__ void fill_csr(const int* __restrict__ src, const int* __restrict__ dst, int e) {
    int i = blockIdx.x * blockDim.x + threadIdx.x;
    if (i < e) {
        int s = src[i], d = dst[i];
        int pos = atomicAdd(&g_cursor[d], 1);
        float w = g_disq[s] * g_disq[d];
        g_csr[pos] = make_int2(s, __float_as_int(w));
    }
}
__global__ void zero_stats() {
    int i = threadIdx.x;
    if (i < 2 * DH) g_stats[i] = 0.0f;
}

// ============ GEMM 128x128 via 3xTF32 tensor cores ============
// 256 threads (8 warps: 2 m x 4 n), warp tile 64x32, block tile 128x128, BK=16.
// Producer-side hi/lo tf32 split: each element split ONCE, stored in fragment-major
// smem (Xhi/Xlo/Whi/Wlo); consumers do pure LDS + MMA (no cvt in inner loop).
// X and W double-buffered per K-chunk; one __syncthreads per chunk; 2 CTAs/SM.
//
// A-frag (m16k8): lane L (g=L>>2, tg=L&3) holds {X[g][tg], X[g+8][tg], X[g][tg+4], X[g+8][tg+4]}
//   frag = 32 lanes * float4 = 128 words, padded to 132.
// B-frag (k8n8):  lane L holds {W[tg][g], W[tg+4][g]} -> 64 words, padded to 66.
#define XFRAG 132
#define WFRAG 66
#define XWORDS (16 * XFRAG)   // 8 tm x 2 ks frags = 2112 words
#define WWORDS (32 * WFRAG)   // 2 ks x 16 nt frags = 2112 words
// Xhi[2][XWORDS], Xlo[2][XWORDS], Whi[2][WWORDS], Wlo[2][WWORDS]
#define GEMM_SMEM_FLOATS (4 * XWORDS + 4 * WWORDS)
#define GEMM_SMEM_BYTES  (GEMM_SMEM_FLOATS * 4)     // 67584 B

__global__ void __launch_bounds__(256, 2) gemm128_tc(const float* __restrict__ Xin,
                                                     const float* __restrict__ W,
                                                     int n, int use_bn) {
    extern __shared__ float smem[];
    float* Xhi = smem;                    // [2][XWORDS]
    float* Xlo = Xhi + 2 * XWORDS;        // [2][XWORDS]
    float* Whi = Xlo + 2 * XWORDS;        // [2][WWORDS]
    float* Wlo = Whi + 2 * WWORDS;        // [2][WWORDS]

    const float* X = Xin ? Xin : g_h;
    int tid  = threadIdx.x;
    int lane = tid & 31;
    int wid  = tid >> 5;
    int warp_m = wid & 1;     // 2 m-halves of 64 rows
    int warp_n = wid >> 1;    // 4 n-quarters of 32 cols
    int row0 = blockIdx.x * 128;

    // ---- producer helpers ----
    auto load_x4 = [&](int kc, int q) -> float4 {
        int xr = q >> 2, xc4 = q & 3;
        int gr = row0 + xr;
        float4 v = make_float4(0.f, 0.f, 0.f, 0.f);
        if (gr < n) v = *(const float4*)(X + (size_t)gr * DH + kc * 16 + xc4 * 4);
        if (use_bn) {
            float4 sc = *(const float4*)(g_scale + kc * 16 + xc4 * 4);
            float4 sh = *(const float4*)(g_shift + kc * 16 + xc4 * 4);
            v.x = fmaxf(0.f, fmaf(v.x, sc.x, sh.x));
            v.y = fmaxf(0.f, fmaf(v.y, sc.y, sh.y));
            v.z = fmaxf(0.f, fmaf(v.z, sc.z, sh.z));
            v.w = fmaxf(0.f, fmaf(v.w, sc.w, sh.w));
        }
        return v;
    };
    auto store_x4 = [&](float4 v, int q, int buf) {
        int xr = q >> 2, xc4 = q & 3;
        int tm = xr >> 4, ri = xr & 15, ks = xc4 >> 1;
        int slot = (ri >> 3) + 2 * (xc4 & 1);
        int lb   = (ri & 7) * 4;
        int base = buf * XWORDS + (tm * 2 + ks) * XFRAG + slot;
        float h0 = tf32_rn(v.x), h1 = tf32_rn(v.y), h2 = tf32_rn(v.z), h3 = tf32_rn(v.w);
        Xhi[base + (lb + 0) * 4] = h0;
        Xhi[base + (lb + 1) * 4] = h1;
        Xhi[base + (lb + 2) * 4] = h2;
        Xhi[base + (lb + 3) * 4] = h3;
        Xlo[base + (lb + 0) * 4] = tf32_rn(v.x - h0);
        Xlo[base + (lb + 1) * 4] = tf32_rn(v.y - h1);
        Xlo[base + (lb + 2) * 4] = tf32_rn(v.z - h2);
        Xlo[base + (lb + 3) * 4] = tf32_rn(v.w - h3);
    };
    auto load_w4 = [&](int kc, int q) -> float4 {
        int kl = q >> 5, c4 = q & 31;
        return *(const float4*)(W + (size_t)(kc * 16 + kl) * DH + c4 * 4);
    };
    auto store_w4 = [&](float4 v, int q, int buf) {
        int kl = q >> 5, c4 = q & 31;
        int ks = (kl >> 3) & 1, slot = (kl >> 2) & 1, kj = kl & 3;
        int nt = c4 >> 1;
        int lb = 16 * (c4 & 1) + kj;   // lane for j=0; lane_j = lb + 4j
        int base = buf * WWORDS + (ks * 16 + nt) * WFRAG + slot;
        float h0 = tf32_rn(v.x), h1 = tf32_rn(v.y), h2 = tf32_rn(v.z), h3 = tf32_rn(v.w);
        Whi[base + (lb + 0)  * 2] = h0;
        Whi[base + (lb + 4)  * 2] = h1;
        Whi[base + (lb + 8)  * 2] = h2;
        Whi[base + (lb + 12) * 2] = h3;
        Wlo[base + (lb + 0)  * 2] = tf32_rn(v.x - h0);
        Wlo[base + (lb + 4)  * 2] = tf32_rn(v.y - h1);
        Wlo[base + (lb + 8)  * 2] = tf32_rn(v.z - h2);
        Wlo[base + (lb + 12) * 2] = tf32_rn(v.w - h3);
    };

    float acc[4][4][4];
#pragma unroll
    for (int mt = 0; mt < 4; mt++)
#pragma unroll
        for (int nt = 0; nt < 4; nt++)
#pragma unroll
            for (int k = 0; k < 4; k++) acc[mt][nt][k] = 0.f;

    // ---- prologue: stage chunk 0 ----
    store_x4(load_x4(0, tid), tid, 0);
    store_x4(load_x4(0, tid + 256), tid + 256, 0);
    store_w4(load_w4(0, tid), tid, 0);
    store_w4(load_w4(0, tid + 256), tid + 256, 0);
    __syncthreads();

    int buf = 0;
    for (int kc = 0; kc < 8; kc++) {
        float4 px0, px1, pw0, pw1;
        if (kc < 7) {
            px0 = load_x4(kc + 1, tid);
            px1 = load_x4(kc + 1, tid + 256);
            pw0 = load_w4(kc + 1, tid);
            pw1 = load_w4(kc + 1, tid + 256);
        }

#pragma unroll
        for (int ks = 0; ks < 2; ks++) {
            float bhi[4][2], blo[4][2];
#pragma unroll
            for (int nt = 0; nt < 4; nt++) {
                int f = buf * WWORDS + (ks * 16 + warp_n * 4 + nt) * WFRAG + lane * 2;
                *(float2*)bhi[nt] = *(const float2*)&Whi[f];
                *(float2*)blo[nt] = *(const float2*)&Wlo[f];
            }
#pragma unroll
            for (int mt = 0; mt < 4; mt++) {
                int f = buf * XWORDS + ((warp_m * 4 + mt) * 2 + ks) * XFRAG + lane * 4;
                float ahi[4], alo[4];
                *(float4*)ahi = *(const float4*)&Xhi[f];
                *(float4*)alo = *(const float4*)&Xlo[f];
#pragma unroll
                for (int nt = 0; nt < 4; nt++) {
                    mma_tf32(acc[mt][nt], ahi, blo[nt]);
                    mma_tf32(acc[mt][nt], alo, bhi[nt]);
                    mma_tf32(acc[mt][nt], ahi, bhi[nt]);
                }
            }
        }

        if (kc < 7) {
            store_x4(px0, tid, buf ^ 1);
            store_x4(px1, tid + 256, buf ^ 1);
            store_w4(pw0, tid, buf ^ 1);
            store_w4(pw1, tid + 256, buf ^ 1);
        }
        __syncthreads();
        buf ^= 1;
    }

    // ---- store result ----
    int g  = lane >> 2;
    int tg = lane & 3;
#pragma unroll
    for (int mt = 0; mt < 4; mt++)
#pragma unroll
        for (int nt = 0; nt < 4; nt++) {
            int r = row0 + warp_m * 64 + mt * 16 + g;
            int c = warp_n * 32 + nt * 8 + tg * 2;
            if (r < n)
                *(float2*)(g_t + (size_t)r * DH + c) =
                    make_float2(acc[mt][nt][0], acc[mt][nt][1]);
            if (r + 8 < n)
                *(float2*)(g_t + (size_t)(r + 8) * DH + c) =
                    make_float2(acc[mt][nt][2], acc[mt][nt][3]);
        }
}

// ---------------- GEMM 128x40 (input = g_h with fused BN+ReLU), writes g_t[n,40] ----------------
__global__ void __launch_bounds__(240) gemm40(const float* __restrict__ W, int n) {
    __shared__ float ws[DH * DOUT];
    __shared__ float xs[48][32];

    int tx  = threadIdx.x;
    int ty  = threadIdx.y;
    int tid = ty * 40 + tx;

    for (int i = tid; i < DH * DOUT; i += 240) ws[i] = W[i];

    int row0 = blockIdx.x * 48;
    float acc[8];
#pragma unroll
    for (int r = 0; r < 8; r++) acc[r] = 0.f;

    for (int kc = 0; kc < 4; kc++) {
        for (int i = tid; i < 384; i += 240) {
            int r  = i >> 3;
            int c4 = i & 7;
            int gr = row0 + r;
            float4 v = make_float4(0.f, 0.f, 0.f, 0.f);
            if (gr < n) v = *(const float4*)(g_h + (size_t)gr * DH + kc * 32 + c4 * 4);
            float4 sc = *(const float4*)(g_scale + kc * 32 + c4 * 4);
            float4 sh = *(const float4*)(g_shift + kc * 32 + c4 * 4);
            v.x = fmaxf(0.f, fmaf(v.x, sc.x, sh.x));
            v.y = fmaxf(0.f, fmaf(v.y, sc.y, sh.y));
            v.z = fmaxf(0.f, fmaf(v.z, sc.z, sh.z));
            v.w = fmaxf(0.f, fmaf(v.w, sc.w, sh.w));
            *(float4*)&xs[r][c4 * 4] = v;
        }
        __syncthreads();
#pragma unroll
        for (int kk = 0; kk < 32; kk++) {
            float wv = ws[(kc * 32 + kk) * DOUT + tx];
#pragma unroll
            for (int r8 = 0; r8 < 8; r8++)
                acc[r8] = fmaf(xs[ty * 8 + r8][kk], wv, acc[r8]);
        }
        __syncthreads();
    }
#pragma unroll
    for (int r8 = 0; r8 < 8; r8++) {
        int gr = row0 + ty * 8 + r8;
        if (gr < n) g_t[(size_t)gr * DOUT + tx] = acc[r8];
    }
}

// ---------------- fused aggregate + combine + BN stats, F=128. One warp per row. ----------------
__global__ void __launch_bounds__(256) agg_combine128(const float* __restrict__ b, int n) {
    int lane = threadIdx.x & 31;
    int wip  = threadIdx.x >> 5;
    const float4* T = (const float4*)g_t;
    float4 bc = ((const float4*)b)[lane];

    float4 ssum = make_float4(0.f, 0.f, 0.f, 0.f);
    float4 ssq  = make_float4(0.f, 0.f, 0.f, 0.f);

    for (int row = blockIdx.x * 8 + wip; row < n; row += gridDim.x * 8) {
        int start = g_rowstart[row];
        int cnt   = g_deg[row];
        float4 acc = make_float4(0.f, 0.f, 0.f, 0.f);
        for (int j = start; j < start + cnt; j++) {
            int2  pr = g_csr[j];
            float w  = __int_as_float(pr.y);
            float4 v = __ldg(T + (size_t)pr.x * 32 + lane);
            acc.x = fmaf(w, v.x, acc.x);
            acc.y = fmaf(w, v.y, acc.y);
            acc.z = fmaf(w, v.z, acc.z);
            acc.w = fmaf(w, v.w, acc.w);
        }
        float dq = g_disq[row];
        float sn = dq * dq;
        float4 t = __ldg(T + (size_t)row * 32 + lane);
        float4 h;
        h.x = fmaf(sn, t.x, acc.x) + bc.x;
        h.y = fmaf(sn, t.y, acc.y) + bc.y;
        h.z = fmaf(sn, t.z, acc.z) + bc.z;
        h.w = fmaf(sn, t.w, acc.w) + bc.w;
        ((float4*)g_h)[(size_t)row * 32 + lane] = h;
        ssum.x += h.x; ssum.y += h.y; ssum.z += h.z; ssum.w += h.w;
        ssq.x = fmaf(h.x, h.x, ssq.x); ssq.y = fmaf(h.y, h.y, ssq.y);
        ssq.z = fmaf(h.z, h.z, ssq.z); ssq.w = fmaf(h.w, h.w, ssq.w);
    }

    __shared__ float4 sh1[8][32];
    __shared__ float4 sh2[8][32];
    sh1[wip][lane] = ssum;
    sh2[wip][lane] = ssq;
    __syncthreads();
    if (wip == 0) {
        float4 a = sh1[0][lane], q = sh2[0][lane];
#pragma unroll
        for (int w = 1; w < 8; w++) {
            float4 a2 = sh1[w][lane], q2 = sh2[w][lane];
            a.x += a2.x; a.y += a2.y; a.z += a2.z; a.w += a2.w;
            q.x += q2.x; q.y += q2.y; q.z += q2.z; q.w += q2.w;
        }
        red_add_v4(g_stats + lane * 4, a);
        red_add_v4(g_stats + DH + lane * 4, q);
    }
}

// ---------------- BN finalize ----------------
__global__ void bn_finalize(const float* __restrict__ gam, const float* __restrict__ bet, int n) {
    int c = threadIdx.x;
    if (c < DH) {
        float inv_n = 1.0f / (float)n;
        float mu  = g_stats[c] * inv_n;
        float var = g_stats[DH + c] * inv_n - mu * mu;
        float rs  = rsqrtf(var + BN_EPS);
        float sc  = rs * gam[c];
        g_scale[c] = sc;
        g_shift[c] = bet[c] - mu * sc;
    }
}

// ---------------- fused aggregate + combine + log_softmax, F=40. One warp per row. ----------------
__global__ void __launch_bounds__(256) agg40_lsm(const float* __restrict__ b2,
                                                 float* __restrict__ out, int n) {
    int lane = threadIdx.x & 31;
    int wip  = threadIdx.x >> 5;
    const float4* T = (const float4*)g_t;
    bool active = (lane < 10);
    float4 bc = make_float4(0.f, 0.f, 0.f, 0.f);
    if (active) bc = ((const float4*)b2)[lane];

    for (int row = blockIdx.x * 8 + wip; row < n; row += gridDim.x * 8) {
        int start = g_rowstart[row];
        int cnt   = g_deg[row];
        float4 acc = make_float4(0.f, 0.f, 0.f, 0.f);
        for (int j = start; j < start + cnt; j++) {
            int2  pr = g_csr[j];
            float w  = __int_as_float(pr.y);
            if (active) {
                float4 v = __ldg(T + (size_t)pr.x * 10 + lane);
                acc.x = fmaf(w, v.x, acc.x);
                acc.y = fmaf(w, v.y, acc.y);
                acc.z = fmaf(w, v.z, acc.z);
                acc.w = fmaf(w, v.w, acc.w);
            }
        }
        float dq = g_disq[row];
        float sn = dq * dq;
        float4 h = make_float4(-1e30f, -1e30f, -1e30f, -1e30f);
        if (active) {
            float4 t = __ldg(T + (size_t)row * 10 + lane);
            h.x = fmaf(sn, t.x, acc.x) + bc.x;
            h.y = fmaf(sn, t.y, acc.y) + bc.y;
            h.z = fmaf(sn, t.z, acc.z) + bc.z;
            h.w = fmaf(sn, t.w, acc.w) + bc.w;
        }
        float m = fmaxf(fmaxf(h.x, h.y), fmaxf(h.z, h.w));
#pragma unroll
        for (int o = 16; o; o >>= 1) m = fmaxf(m, __shfl_xor_sync(0xFFFFFFFFu, m, o));
        float se = 0.f;
        if (active)
            se = expf(h.x - m) + expf(h.y - m) + expf(h.z - m) + expf(h.w - m);
#pragma unroll
        for (int o = 16; o; o >>= 1) se += __shfl_xor_sync(0xFFFFFFFFu, se, o);
        float lse = m + logf(se);
        if (active) {
            float4 r = make_float4(h.x - lse, h.y - lse, h.z - lse, h.w - lse);
            ((float4*)out)[(size_t)row * 10 + lane] = r;
        }
    }
}

// ---------------- launch ----------------
extern "C" void kernel_launch(void* const* d_in, const int* in_sizes, int n_in,
                              void* d_out, int out_size) {
    const float* x   = (const float*)d_in[0];
    const int*   src = (const int*)d_in[1];
    const int*   dst = (const int*)d_in[2];
    const float* W0  = (const float*)d_in[3];
    const float* b0  = (const float*)d_in[4];
    const float* W1  = (const float*)d_in[5];
    const float* b1  = (const float*)d_in[6];
    const float* W2  = (const float*)d_in[7];
    const float* b2  = (const float*)d_in[8];
    const float* g0  = (const float*)d_in[9];
    const float* be0 = (const float*)d_in[10];
    const float* g1  = (const float*)d_in[11];
    const float* be1 = (const float*)d_in[12];
    float* out = (float*)d_out;

    int n = in_sizes[0] / DH;
    int e = in_sizes[1];
    int nb = (n + SCAN_B - 1) / SCAN_B;

    int agg_blocks  = 1480;
    int gemm_blocks = (n + 127) / 128;

    cudaFuncSetAttribute(gemm128_tc, cudaFuncAttributeMaxDynamicSharedMemorySize,
                         GEMM_SMEM_BYTES);

    // ---- CSR build (layer-0 GEMM interleaved at launch index 3 for profiling) ----
    zero_deg<<<(n + 255) / 256, 256>>>(n);
    count_deg<<<(e + 255) / 256, 256>>>(dst, e);
    calc_disq<<<(n + 255) / 256, 256>>>(n);
    gemm128_tc<<<gemm_blocks, 256, GEMM_SMEM_BYTES>>>(x, W0, n, 0);
    scan1<<<nb, SCAN_B>>>(n);
    scan2<<<1, NB_MAX>>>(nb);
    scan3<<<(n + 255) / 256, 256>>>(n);
    fill_csr<<<(e + 255) / 256, 256>>>(src, dst, e);

    // ---- layer 0 (agg part) ----
    zero_stats<<<1, 256>>>();
    agg_combine128<<<agg_blocks, 256>>>(b0, n);
    bn_finalize<<<1, DH>>>(g0, be0, n);

    // ---- layer 1 ----
    gemm128_tc<<<gemm_blocks, 256, GEMM_SMEM_BYTES>>>(nullptr, W1, n, 1);
    zero_stats<<<1, 256>>>();
    agg_combine128<<<agg_blocks, 256>>>(b1, n);
    bn_finalize<<<1, DH>>>(g1, be1, n);

    // ---- layer 2 ----
    gemm40<<<(n + 47) / 48, dim3(DOUT, 6)>>>(W2, n);
    agg40_lsm<<<agg_blocks, 256>>>(b2, out, n);
}